// round 5
// baseline (speedup 1.0000x reference)
#include <cuda_runtime.h>
#include <math.h>

// Scratch (static device globals; allocation-free)
__device__ float g_Ahat[1024 * 176];          // [i][h*44+k] = [Q*scale | w*Qg]
__device__ float g_BhatT[44 * 1024 * 4];      // [k4][j][4]  = [K | Kg] transposed
__device__ float g_cjh[1024 * 4];             // [j][h] -0.5*w*|Kg|^2
__device__ float g_Vcat[1024 * 176];          // [j][ V(128) | Vg(48) ]
__device__ float g_bat[(size_t)1024 * 1024 * 4];  // [i][j][h] pair@Wb (16MB)
__device__ float g_attn[(size_t)4 * 1024 * 1024]; // [h][i][j] normalized (16MB)
__device__ float g_os[1024 * 128];
__device__ float g_optg[1024 * 48];
__device__ float g_opair[1024 * 256];

// ---------------------------------------------------------------------------
// kmix1: block-role merged kernel.
//   blocks [0, 4096):   kbias  — b = pair@Wb, 2x128-row tiles per block
//   blocks [4096, 4352): kprep — layernorm + projections + frames (4 rows)
// blk=256, dyn smem 70656 B
// ---------------------------------------------------------------------------
__global__ __launch_bounds__(256) void kmix1(
    const float* __restrict__ pair,   const float* __restrict__ Wb,
    const float* __restrict__ single, const float* __restrict__ T,
    const float* __restrict__ w_C,    const float* __restrict__ ln_g,
    const float* __restrict__ ln_b,
    const float* __restrict__ Wq, const float* __restrict__ Wk,
    const float* __restrict__ Wv, const float* __restrict__ Wqpt,
    const float* __restrict__ Wkpt, const float* __restrict__ Wvpt)
{
    extern __shared__ float sm[];
    const int t = threadIdx.x;

    if (blockIdx.x < 4096) {
        // ---------------- kbias branch: two 128-row tiles ----------------
        float* wbs = sm;            // 256
        float* ps  = sm + 256;      // 2 * 128*68

        const int half = t >> 7;          // 0/1
        const int tt   = t & 127;
        float* myps = ps + half * (128 * 68);
        const size_t base = (size_t)blockIdx.x * 256 + half * 128;

        if (t < 256) { if (t < 256) wbs[t] = Wb[t]; }

        const float4* src = (const float4*)(pair + base * 64);
        #pragma unroll
        for (int q = 0; q < 16; q++) {
            int u = q * 128 + tt;
            float4 v = src[u];
            int row = u >> 4, c4 = u & 15;
            *(float4*)&myps[row * 68 + c4 * 4] = v;
        }
        __syncthreads();

        float b0 = 0.f, b1 = 0.f, b2 = 0.f, b3 = 0.f;
        #pragma unroll
        for (int k = 0; k < 16; k++) {
            float4 q = *(const float4*)&myps[tt * 68 + k * 4];
            const float* w = wbs + k * 16;
            b0 += q.x * w[0] + q.y * w[4] + q.z * w[8]  + q.w * w[12];
            b1 += q.x * w[1] + q.y * w[5] + q.z * w[9]  + q.w * w[13];
            b2 += q.x * w[2] + q.y * w[6] + q.z * w[10] + q.w * w[14];
            b3 += q.x * w[3] + q.y * w[7] + q.z * w[11] + q.w * w[15];
        }
        ((float4*)g_bat)[base + tt] = make_float4(b0, b1, b2, b3);
        return;
    }

    // ---------------- kprep branch ----------------
    float* zs   = sm;               // 512   [d][r]
    float* proj = sm + 512;         // 4*528 [r][o]
    float* red  = sm + 512 + 2112;  // 16

    const int i0 = (blockIdx.x - 4096) * 4;
    const int lane = t & 31, wid = t >> 5;

    for (int pass = 0; pass < 2; pass++) {
        const int r = pass * 2 + (t >> 7);
        const int d = t & 127;
        float x = single[(i0 + r) * 128 + d];
        float s = x, s2 = x * x;
        #pragma unroll
        for (int o = 16; o; o >>= 1) {
            s  += __shfl_xor_sync(0xffffffffu, s,  o);
            s2 += __shfl_xor_sync(0xffffffffu, s2, o);
        }
        if (lane == 0) { red[wid] = s; red[8 + wid] = s2; }
        __syncthreads();
        const int base = (t >> 7) * 4;
        float sum  = red[base] + red[base+1] + red[base+2] + red[base+3];
        float sum2 = red[8+base] + red[8+base+1] + red[8+base+2] + red[8+base+3];
        float mu  = sum * (1.f / 128.f);
        float var = sum2 * (1.f / 128.f) - mu * mu;
        float inv = rsqrtf(var + 1e-5f);
        zs[d * 4 + r] = (x - mu) * inv * ln_g[d] + ln_b[d];
        __syncthreads();
    }

    for (int o = t; o < 528; o += 256) {
        const float* W; int col, ow;
        if      (o < 128) { W = Wq;   col = o;       ow = 128; }
        else if (o < 256) { W = Wk;   col = o - 128; ow = 128; }
        else if (o < 384) { W = Wv;   col = o - 256; ow = 128; }
        else if (o < 432) { W = Wqpt; col = o - 384; ow = 48;  }
        else if (o < 480) { W = Wkpt; col = o - 432; ow = 48;  }
        else              { W = Wvpt; col = o - 480; ow = 48;  }
        float a0 = 0.f, a1 = 0.f, a2 = 0.f, a3 = 0.f;
        #pragma unroll 8
        for (int d = 0; d < 128; d++) {
            float w = W[d * ow + col];
            float4 z = *(const float4*)&zs[d * 4];
            a0 += z.x * w; a1 += z.y * w; a2 += z.z * w; a3 += z.w * w;
        }
        proj[0 * 528 + o] = a0; proj[1 * 528 + o] = a1;
        proj[2 * 528 + o] = a2; proj[3 * 528 + o] = a3;
    }
    __syncthreads();

    const float scale = 0.17677669529663687f;   // 1/sqrt(32)
    for (int u = t; u < 512; u += 256) {
        int r = u >> 7, k = u & 127;
        int i = i0 + r, h = k >> 5, d = k & 31;
        int kk = h * 44 + d;
        g_Ahat[i * 176 + kk] = proj[r * 528 + k] * scale;
        g_BhatT[(kk >> 2) * 4096 + i * 4 + (kk & 3)] = proj[r * 528 + 128 + k];
        g_Vcat[i * 176 + k] = proj[r * 528 + 256 + k];
    }

    if (t < 16) {
        int r = t >> 2, h = t & 3;
        int i = i0 + r;
        float w = log1pf(__expf(w_C[h]));
        float R[3][3], tv[3];
        #pragma unroll
        for (int x = 0; x < 3; x++) {
            #pragma unroll
            for (int y = 0; y < 3; y++) R[x][y] = T[i * 16 + x * 4 + y];
            tv[x] = T[i * 16 + x * 4 + 3];
        }
        float kk2 = 0.f;
        #pragma unroll
        for (int p = 0; p < 4; p++) {
            float q0 = proj[r * 528 + 384 + h * 12 + p * 3 + 0];
            float q1 = proj[r * 528 + 384 + h * 12 + p * 3 + 1];
            float q2 = proj[r * 528 + 384 + h * 12 + p * 3 + 2];
            float k0 = proj[r * 528 + 432 + h * 12 + p * 3 + 0];
            float k1 = proj[r * 528 + 432 + h * 12 + p * 3 + 1];
            float k2 = proj[r * 528 + 432 + h * 12 + p * 3 + 2];
            float v0 = proj[r * 528 + 480 + h * 12 + p * 3 + 0];
            float v1 = proj[r * 528 + 480 + h * 12 + p * 3 + 1];
            float v2 = proj[r * 528 + 480 + h * 12 + p * 3 + 2];
            #pragma unroll
            for (int x = 0; x < 3; x++) {
                float gq = R[x][0] * q0 + R[x][1] * q1 + R[x][2] * q2 + tv[x];
                float gk = R[x][0] * k0 + R[x][1] * k1 + R[x][2] * k2 + tv[x];
                float gv = R[x][0] * v0 + R[x][1] * v1 + R[x][2] * v2 + tv[x];
                int kki = h * 44 + 32 + p * 3 + x;
                g_Ahat[i * 176 + kki] = w * gq;
                g_BhatT[(kki >> 2) * 4096 + i * 4 + (kki & 3)] = gk;
                g_Vcat[i * 176 + 128 + h * 12 + p * 3 + x] = gv;
                kk2 += gk * gk;
            }
        }
        g_cjh[i * 4 + h] = -0.5f * w * kk2;
    }
}

// ---------------------------------------------------------------------------
// klogits: logits + softmax -> normalized probs to g_attn[h][i][j].
// grid=256 (4 rows/block), blk=256, dyn smem ~68KB
// ---------------------------------------------------------------------------
__global__ __launch_bounds__(256) void klogits()
{
    extern __shared__ float smem[];
    float* probs = smem;               // 16384  [r*4+h][1024]
    float* Ahat  = smem + 16384;       // 704
    float* redm  = Ahat + 704;         // 128 [wid][16]
    float* reds  = redm + 128;         // 128

    const int t = threadIdx.x;
    const int i0 = blockIdx.x * 4;
    const int lane = t & 31, wid = t >> 5;

    for (int u = t; u < 704; u += 256) Ahat[u] = g_Ahat[i0 * 176 + u];
    __syncthreads();

    const float4* bhat4 = (const float4*)g_BhatT;
    const float4* bat4  = (const float4*)g_bat;
    const float4* cjh4  = (const float4*)g_cjh;

    for (int jj = 0; jj < 4; jj++) {
        int j = jj * 256 + t;
        float acc[4][4];
        #pragma unroll
        for (int r = 0; r < 4; r++)
            #pragma unroll
            for (int h = 0; h < 4; h++) acc[r][h] = 0.f;

        #pragma unroll
        for (int k4 = 0; k4 < 44; k4++) {
            const int h = k4 / 11;
            float4 bv = bhat4[k4 * 1024 + j];
            #pragma unroll
            for (int r = 0; r < 4; r++) {
                float4 av = *(const float4*)&Ahat[r * 176 + k4 * 4];
                acc[r][h] += av.x * bv.x + av.y * bv.y + av.z * bv.z + av.w * bv.w;
            }
        }
        float4 cj = cjh4[j];
        #pragma unroll
        for (int r = 0; r < 4; r++) {
            float4 bb = bat4[(size_t)(i0 + r) * 1024 + j];
            probs[(r * 4 + 0) * 1024 + j] = acc[r][0] + bb.x + cj.x;
            probs[(r * 4 + 1) * 1024 + j] = acc[r][1] + bb.y + cj.y;
            probs[(r * 4 + 2) * 1024 + j] = acc[r][2] + bb.z + cj.z;
            probs[(r * 4 + 3) * 1024 + j] = acc[r][3] + bb.w + cj.w;
        }
    }
    __syncthreads();

    float mx[16];
    #pragma unroll
    for (int rh = 0; rh < 16; rh++) {
        float m = -1e30f;
        #pragma unroll
        for (int jj = 0; jj < 4; jj++) m = fmaxf(m, probs[rh * 1024 + jj * 256 + t]);
        #pragma unroll
        for (int o = 16; o; o >>= 1) m = fmaxf(m, __shfl_xor_sync(0xffffffffu, m, o));
        if (lane == 0) redm[wid * 16 + rh] = m;
    }
    __syncthreads();
    #pragma unroll
    for (int rh = 0; rh < 16; rh++) {
        float m = redm[rh];
        #pragma unroll
        for (int w = 1; w < 8; w++) m = fmaxf(m, redm[w * 16 + rh]);
        mx[rh] = m;
    }
    #pragma unroll
    for (int rh = 0; rh < 16; rh++) {
        float s = 0.f;
        #pragma unroll
        for (int jj = 0; jj < 4; jj++) {
            int j = jj * 256 + t;
            float e = __expf(probs[rh * 1024 + j] - mx[rh]);
            probs[rh * 1024 + j] = e;
            s += e;
        }
        #pragma unroll
        for (int o = 16; o; o >>= 1) s += __shfl_xor_sync(0xffffffffu, s, o);
        if (lane == 0) reds[wid * 16 + rh] = s;
    }
    __syncthreads();
    float invZ[16];
    #pragma unroll
    for (int rh = 0; rh < 16; rh++) {
        float s = 0.f;
        #pragma unroll
        for (int w = 0; w < 8; w++) s += reds[w * 16 + rh];
        invZ[rh] = 1.0f / s;
    }

    #pragma unroll
    for (int jj = 0; jj < 4; jj++) {
        int j = jj * 256 + t;
        #pragma unroll
        for (int r = 0; r < 4; r++)
            #pragma unroll
            for (int h = 0; h < 4; h++)
                g_attn[((size_t)h * 1024 + (i0 + r)) * 1024 + j] =
                    probs[(r * 4 + h) * 1024 + j] * invZ[r * 4 + h];
    }
}

// ---------------------------------------------------------------------------
// kmix2: block-role merged kernel. blk=512, dyn smem 32KB
//   blocks [0, 1024):    kopair — o_pair = attn @ pair (8 j-groups)
//   blocks [1024, 1280): kattnv — o_s = attn@V, o_pt_g = attn@Vg
// ---------------------------------------------------------------------------
__global__ __launch_bounds__(512) void kmix2(const float* __restrict__ pair)
{
    extern __shared__ float sm2[];
    const int t = threadIdx.x;

    if (blockIdx.x < 1024) {
        // -------- kopair branch --------
        float* ps  = sm2;          // 4096 [h][j]
        float* red = sm2 + 4096;   // 8*4*64 = 2048

        const int i = blockIdx.x;
        #pragma unroll
        for (int q = 0; q < 8; q++) {
            int u = q * 512 + t;
            ps[u] = g_attn[((size_t)(u >> 10) * 1024 + i) * 1024 + (u & 1023)];
        }
        __syncthreads();

        const int c = t & 63, g = t >> 6;      // g in [0,8)
        const float* prow = pair + (size_t)i * 65536 + c;
        float acc[4] = {0.f, 0.f, 0.f, 0.f};

        for (int j = g; j < 1024; j += 32) {
            float p0 = prow[(j + 0)  * 64];
            float p1 = prow[(j + 8)  * 64];
            float p2 = prow[(j + 16) * 64];
            float p3 = prow[(j + 24) * 64];
            #pragma unroll
            for (int h = 0; h < 4; h++) {
                acc[h] += ps[h * 1024 + j]      * p0
                        + ps[h * 1024 + j + 8]  * p1
                        + ps[h * 1024 + j + 16] * p2
                        + ps[h * 1024 + j + 24] * p3;
            }
        }
        #pragma unroll
        for (int h = 0; h < 4; h++) red[(g * 4 + h) * 64 + c] = acc[h];
        __syncthreads();
        if (t < 256) {
            const int c2 = t & 63, h2 = t >> 6;
            float s = 0.f;
            #pragma unroll
            for (int g2 = 0; g2 < 8; g2++) s += red[(g2 * 4 + h2) * 64 + c2];
            g_opair[i * 256 + h2 * 64 + c2] = s;
        }
        return;
    }

    // -------- kattnv branch --------
    float* As = sm2;           // [16][129] = 2064
    float* Vs = sm2 + 2064;    // [128][45] = 5760

    const int bid2 = blockIdx.x - 1024;
    const int h  = bid2 & 3;
    const int i0 = (bid2 >> 2) * 16;
    const int r  = t & 15;
    const int n  = (t >> 4) & 31;     // 0..31
    const int n2 = 32 + (n < 12 ? n : 0);

    float acc0 = 0.f, acc1 = 0.f;

    for (int j0 = 0; j0 < 1024; j0 += 128) {
        __syncthreads();
        if (t < 128) {
            int jj = t;
            const float4* vp = (const float4*)(g_Vcat + (size_t)(j0 + jj) * 176 + h * 32);
            #pragma unroll
            for (int q = 0; q < 8; q++) {
                float4 v = vp[q];
                Vs[jj * 45 + q * 4 + 0] = v.x; Vs[jj * 45 + q * 4 + 1] = v.y;
                Vs[jj * 45 + q * 4 + 2] = v.z; Vs[jj * 45 + q * 4 + 3] = v.w;
            }
            const float4* gp = (const float4*)(g_Vcat + (size_t)(j0 + jj) * 176 + 128 + h * 12);
            #pragma unroll
            for (int q = 0; q < 3; q++) {
                float4 v = gp[q];
                Vs[jj * 45 + 32 + q * 4 + 0] = v.x; Vs[jj * 45 + 32 + q * 4 + 1] = v.y;
                Vs[jj * 45 + 32 + q * 4 + 2] = v.z; Vs[jj * 45 + 32 + q * 4 + 3] = v.w;
            }
        } else if (t < 384) {
            int t2 = t - 128;
            #pragma unroll
            for (int q = 0; q < 8; q++) {
                int u = q * 256 + t2;
                int rr = u >> 7, jj = u & 127;
                As[rr * 129 + jj] = g_attn[((size_t)h * 1024 + (i0 + rr)) * 1024 + j0 + jj];
            }
        }
        __syncthreads();
        #pragma unroll 8
        for (int jj = 0; jj < 128; jj++) {
            float a = As[r * 129 + jj];
            acc0 += a * Vs[jj * 45 + n];
            acc1 += a * Vs[jj * 45 + n2];
        }
    }
    int i = i0 + r;
    g_os[i * 128 + h * 32 + n] = acc0;
    if (n < 12) g_optg[i * 48 + h * 12 + n] = acc1;
}

// ---------------------------------------------------------------------------
// kfinal: rotation+norm, concat, out = single + f@Wout + b_out.
// grid=256 (4 rows/block), blk=512
// ---------------------------------------------------------------------------
__global__ __launch_bounds__(512) void kfinal(
    const float* __restrict__ single, const float* __restrict__ T,
    const float* __restrict__ Wout,   const float* __restrict__ b_out,
    float* __restrict__ out)
{
    __shared__ float fs[448 * 4];        // [k][r]
    __shared__ float part[4 * 4 * 128];  // [quarter][r][d]

    const int t  = threadIdx.x;
    const int i0 = blockIdx.x * 4;

    {
        int r = t & 3, k = t >> 2;
        fs[k * 4 + r] = g_os[(i0 + r) * 128 + k];
    }
    for (int u = t; u < 1024; u += 512) {
        int r = u & 3, k2 = u >> 2;
        fs[(128 + k2) * 4 + r] = g_opair[(i0 + r) * 256 + k2];
    }
    if (t < 64) {
        int r = t >> 4, hp = t & 15, h = hp >> 2, p = hp & 3;
        int i = i0 + r;
        float Rm[3][3], tv[3];
        #pragma unroll
        for (int y = 0; y < 3; y++) {
            #pragma unroll
            for (int x = 0; x < 3; x++) Rm[y][x] = T[i * 16 + y * 4 + x];
            tv[y] = T[i * 16 + y * 4 + 3];
        }
        float g0 = g_optg[i * 48 + h * 12 + p * 3 + 0] - tv[0];
        float g1 = g_optg[i * 48 + h * 12 + p * 3 + 1] - tv[1];
        float g2 = g_optg[i * 48 + h * 12 + p * 3 + 2] - tv[2];
        float nrm = 0.f;
        #pragma unroll
        for (int x = 0; x < 3; x++) {
            float v = Rm[0][x] * g0 + Rm[1][x] * g1 + Rm[2][x] * g2;
            fs[(384 + h * 12 + p * 3 + x) * 4 + r] = v;
            nrm += v * v;
        }
        fs[(432 + h * 4 + p) * 4 + r] = sqrtf(nrm);
    }
    __syncthreads();

    const int d = t & 127, q = t >> 7;
    float a0 = 0.f, a1 = 0.f, a2 = 0.f, a3 = 0.f;
    const int k0 = q * 112;
    #pragma unroll 8
    for (int k = k0; k < k0 + 112; k++) {
        float w = Wout[k * 128 + d];
        float4 f = *(const float4*)&fs[k * 4];
        a0 += f.x * w; a1 += f.y * w; a2 += f.z * w; a3 += f.w * w;
    }
    part[(q * 4 + 0) * 128 + d] = a0;
    part[(q * 4 + 1) * 128 + d] = a1;
    part[(q * 4 + 2) * 128 + d] = a2;
    part[(q * 4 + 3) * 128 + d] = a3;
    __syncthreads();

    {
        const int r = t >> 7, dd = t & 127;
        float s = part[(0 * 4 + r) * 128 + dd] + part[(1 * 4 + r) * 128 + dd]
                + part[(2 * 4 + r) * 128 + dd] + part[(3 * 4 + r) * 128 + dd];
        out[(i0 + r) * 128 + dd] = single[(i0 + r) * 128 + dd] + s + b_out[dd];
    }
}

// ---------------------------------------------------------------------------
extern "C" void kernel_launch(void* const* d_in, const int* in_sizes, int n_in,
                              void* d_out, int out_size)
{
    const float* single = (const float*)d_in[0];
    const float* pair   = (const float*)d_in[1];
    const float* T      = (const float*)d_in[2];
    const float* w_C    = (const float*)d_in[3];
    const float* ln_g   = (const float*)d_in[4];
    const float* ln_b   = (const float*)d_in[5];
    const float* Wq     = (const float*)d_in[6];
    const float* Wk     = (const float*)d_in[7];
    const float* Wv     = (const float*)d_in[8];
    const float* Wqpt   = (const float*)d_in[9];
    const float* Wkpt   = (const float*)d_in[10];
    const float* Wvpt   = (const float*)d_in[11];
    const float* Wb     = (const float*)d_in[12];
    const float* Wout   = (const float*)d_in[13];
    const float* b_out  = (const float*)d_in[14];
    float* out = (float*)d_out;

    const int kmix1_smem   = (256 + 2 * 128 * 68) * 4;            // 70656 B
    const int klogits_smem = (16384 + 704 + 128 + 128) * 4;       // 69376 B
    const int kmix2_smem   = (2064 + 5760) * 4;                   // 31296 B

    static int smem_set = 0;
    if (!smem_set) {
        cudaFuncSetAttribute(kmix1, cudaFuncAttributeMaxDynamicSharedMemorySize,
                             kmix1_smem);
        cudaFuncSetAttribute(klogits, cudaFuncAttributeMaxDynamicSharedMemorySize,
                             klogits_smem);
        smem_set = 1;
    }

    kmix1<<<4352, 256, kmix1_smem>>>(pair, Wb, single, T, w_C, ln_g, ln_b,
                                     Wq, Wk, Wv, Wqpt, Wkpt, Wvpt);
    klogits<<<256, 256, klogits_smem>>>();
    kmix2<<<1280, 512, kmix2_smem>>>(pair);
    kfinal<<<256, 512>>>(single, T, Wout, b_out, out);
}